// round 11
// baseline (speedup 1.0000x reference)
#include <cuda_runtime.h>
#include <math.h>

// Problem constants (fixed shapes from reference)
#define B_    4
#define S_    4096
#define H_    16
#define D_    128
#define HALF_ 64
#define MAX_OFFSET_ 512

// inv_freq passed by value (constant space), computed on host in double.
struct InvFreq { float v[HALF_]; };

struct Row6 { float4 q1, q2, k1, k2, v1, v2; };

__device__ __forceinline__ Row6 load_pos(const float4* __restrict__ qkv, int qoff) {
    Row6 t;
    t.q1 = __ldcs(&qkv[qoff]);
    t.q2 = __ldcs(&qkv[qoff + 16]);
    t.k1 = __ldcs(&qkv[qoff + 512]);        // +16*32
    t.k2 = __ldcs(&qkv[qoff + 512 + 16]);
    t.v1 = __ldcs(&qkv[qoff + 1024]);       // +32*32
    t.v2 = __ldcs(&qkv[qoff + 1024 + 16]);
    return t;
}

// Rotate + store one position. cos/sin via 2 sincosf + 8 shuffles (identical
// numerics to reference: fp32 inv_freq, fp32 pos*inv, accurate sincosf).
__device__ __forceinline__ void process_pos(
    float4* __restrict__ out, const Row6& t, int qoff,
    float fpos, float fi_lo, float fi_hi, int l0, int l1)
{
    const unsigned FULL = 0xFFFFFFFFu;
    float c_lo, s_lo, c_hi, s_hi;
    sincosf(fpos * fi_lo, &s_lo, &c_lo);
    sincosf(fpos * fi_hi, &s_hi, &c_hi);
    float4 c, sn;
    c.x  = __shfl_sync(FULL, c_lo, l0);
    c.y  = __shfl_sync(FULL, c_hi, l0);
    c.z  = __shfl_sync(FULL, c_lo, l1);
    c.w  = __shfl_sync(FULL, c_hi, l1);
    sn.x = __shfl_sync(FULL, s_lo, l0);
    sn.y = __shfl_sync(FULL, s_hi, l0);
    sn.z = __shfl_sync(FULL, s_lo, l1);
    sn.w = __shfl_sync(FULL, s_hi, l1);

    float4 o1, o2;
    o1.x = fmaf(t.q1.x, c.x, -t.q2.x * sn.x);
    o1.y = fmaf(t.q1.y, c.y, -t.q2.y * sn.y);
    o1.z = fmaf(t.q1.z, c.z, -t.q2.z * sn.z);
    o1.w = fmaf(t.q1.w, c.w, -t.q2.w * sn.w);
    o2.x = fmaf(t.q1.x, sn.x, t.q2.x * c.x);
    o2.y = fmaf(t.q1.y, sn.y, t.q2.y * c.y);
    o2.z = fmaf(t.q1.z, sn.z, t.q2.z * c.z);
    o2.w = fmaf(t.q1.w, sn.w, t.q2.w * c.w);
    __stcs(&out[qoff],      o1);
    __stcs(&out[qoff + 16], o2);

    o1.x = fmaf(t.k1.x, c.x, -t.k2.x * sn.x);
    o1.y = fmaf(t.k1.y, c.y, -t.k2.y * sn.y);
    o1.z = fmaf(t.k1.z, c.z, -t.k2.z * sn.z);
    o1.w = fmaf(t.k1.w, c.w, -t.k2.w * sn.w);
    o2.x = fmaf(t.k1.x, sn.x, t.k2.x * c.x);
    o2.y = fmaf(t.k1.y, sn.y, t.k2.y * c.y);
    o2.z = fmaf(t.k1.z, sn.z, t.k2.z * c.z);
    o2.w = fmaf(t.k1.w, sn.w, t.k2.w * c.w);
    __stcs(&out[qoff + 512],      o1);
    __stcs(&out[qoff + 512 + 16], o2);

    __stcs(&out[qoff + 1024],      t.v1);
    __stcs(&out[qoff + 1024 + 16], t.v2);
}

// One block per FOUR consecutive (b, s) positions (S divisible by 4 -> never
// crosses batch). Software-pipelined: preload pos0+pos1 (12 LDG in flight),
// then each process phase issues the next position's 6 loads BEFORE the
// stores, keeping ~12 loads perpetually outstanding through the R/W
// turnarounds instead of only at block start.
__global__ void __launch_bounds__(256) rope_fused4_kernel(
    const float4* __restrict__ qkv,
    const int*    __restrict__ offsets,
    float4*       __restrict__ out,
    InvFreq       inv)
{
    int bs0  = blockIdx.x << 2;      // first of 4 positions
    int tid  = threadIdx.x;
    int lane = tid & 31;
    int j    = tid & 15;             // float4 index within the half
    int r    = tid >> 4;             // head row within q-group [0,16)

    // float4 index of q row at pos0; position stride = 1536; max < 2^31
    int q0 = bs0 * 1536 + r * 32 + j;

    // Prologue: preload positions 0 and 1
    Row6 t0 = load_pos(qkv, q0);
    Row6 t1 = load_pos(qkv, q0 + 1536);

    int b    = bs0 >> 12;            // S = 4096
    int s0   = bs0 & (S_ - 1);
    float fpos = (float)(offsets[b] + s0);

    float fi_lo = inv.v[2 * lane];
    float fi_hi = inv.v[2 * lane + 1];
    int l0 = 2 * j, l1 = 2 * j + 1;

    // Steady state: issue loads for pos i+2, then process+store pos i
    Row6 t2 = load_pos(qkv, q0 + 2 * 1536);
    process_pos(out, t0, q0, fpos, fi_lo, fi_hi, l0, l1);

    Row6 t3 = load_pos(qkv, q0 + 3 * 1536);
    process_pos(out, t1, q0 + 1536, fpos + 1.0f, fi_lo, fi_hi, l0, l1);

    process_pos(out, t2, q0 + 2 * 1536, fpos + 2.0f, fi_lo, fi_hi, l0, l1);
    process_pos(out, t3, q0 + 3 * 1536, fpos + 3.0f, fi_lo, fi_hi, l0, l1);
}

extern "C" void kernel_launch(void* const* d_in, const int* in_sizes, int n_in,
                              void* d_out, int out_size) {
    const float4* qkv     = (const float4*)d_in[0];
    const int*    offsets = (const int*)d_in[1];
    float4*       out     = (float4*)d_out;

    // Host-side inv_freq: double precision, rounded to fp32 (same numerics
    // as before). Deterministic; 64 floats passed by value.
    InvFreq inv;
    for (int i = 0; i < HALF_; i++) {
        inv.v[i] = (float)exp(-log(10000.0) * ((double)i / 64.0));
    }

    rope_fused4_kernel<<<(B_ * S_) / 4, 256>>>(qkv, offsets, out, inv);
}